// round 3
// baseline (speedup 1.0000x reference)
#include <cuda_runtime.h>
#include <cuda_bf16.h>
#include <math.h>

// ---------------------------------------------------------------------------
// DKVMN: B=64, L=200, D=128, M=50, FIX=512, NUM_C=10000. Rows = B*L = 12800.
// Pipeline:
//   k = k_emb[q] @ W1 + b1                       (gather GEMM, K=512)
//   v = v_emb[q+10000r] @ W2 + b2                (gather GEMM, K=512)
//   w = softmax(k @ Mk^T)   [rows x 50]
//   e = sigmoid(v @ We + be), a = tanh(v @ Wa + ba)   (GEMM K=128)
//   scan over L: r_t = w_t . Mv ; Mv += w (x) (a - e*Mv)
//   p = sigmoid(tanh([r|k] @ Wf + bf) @ Wp + bp)      (GEMM K=256, fused head)
// ---------------------------------------------------------------------------

#define NROWS 12800

__device__ float g_k[NROWS * 128];
__device__ float g_v[NROWS * 128];
__device__ float g_e[NROWS * 128];
__device__ float g_a[NROWS * 128];
__device__ float g_reads[NROWS * 128];
__device__ float g_w[NROWS * 64];   // pitch 64, 50 valid

// ---------------------------------------------------------------------------
// Generic 64x128 tile GEMM:  C[64,128] = act( A[64,KDIM] @ W[KDIM,128] + bias )
// IDX: 0 = direct row (lda=128), 1 = gather q (lda=512), 2 = gather q+10000r
// KDIM==256 splits columns: [0,128) from A, [128,256) from A2 (concat).
// ACT: 0=none, 1=sigmoid, 2=tanh, 3=tanh then fused p = sigmoid(f.Wp + bp)
// ---------------------------------------------------------------------------
template <int KDIM, int IDX, int ACT>
__global__ __launch_bounds__(256) void gemm64x128(
    const float* __restrict__ A, const float* __restrict__ A2,
    const int* __restrict__ qi, const int* __restrict__ ri,
    const float* __restrict__ W, const float* __restrict__ bias,
    float* __restrict__ C, const float* __restrict__ Wp,
    const float* __restrict__ bp)
{
    __shared__ float As[16][68];
    __shared__ float Bs[16][128];
    __shared__ float pbuf[64][17];

    const int t  = threadIdx.x;
    const int bi = blockIdx.x;
    const int cx = t & 15;        // 16 col-groups of 8
    const int ry = t >> 4;        // 16 row-groups of 4
    const int lrow = t >> 2;      // A-load row
    const int c4   = t & 3;       // A-load float4 slot
    const int grow_l = bi * 64 + lrow;

    size_t arow;
    if (IDX == 1)      arow = (size_t)qi[grow_l];
    else if (IDX == 2) arow = (size_t)qi[grow_l] + (size_t)10000 * (size_t)ri[grow_l];
    else               arow = (size_t)grow_l;
    const int lda = (IDX == 0) ? 128 : 512;

    float acc[4][8];
#pragma unroll
    for (int i = 0; i < 4; i++)
#pragma unroll
        for (int j = 0; j < 8; j++) acc[i][j] = 0.f;

    for (int kt = 0; kt < KDIM / 16; ++kt) {
        // ---- load A tile (64 x 16), transposed into As[k][row] ----
        {
            int gc = kt * 16 + c4 * 4;
            const float* abase = A;
            int cc = gc;
            if (KDIM == 256 && gc >= 128) { abase = A2; cc = gc - 128; }
            float4 av = *reinterpret_cast<const float4*>(abase + arow * (size_t)lda + cc);
            As[c4 * 4 + 0][lrow] = av.x;
            As[c4 * 4 + 1][lrow] = av.y;
            As[c4 * 4 + 2][lrow] = av.z;
            As[c4 * 4 + 3][lrow] = av.w;
        }
        // ---- load B tile (16 x 128) ----
#pragma unroll
        for (int u = 0; u < 2; ++u) {
            int e  = t + u * 256;
            int rr = e >> 5, cb = e & 31;
            float4 bv = *reinterpret_cast<const float4*>(W + (size_t)(kt * 16 + rr) * 128 + cb * 4);
            *reinterpret_cast<float4*>(&Bs[rr][cb * 4]) = bv;
        }
        __syncthreads();
        // ---- compute ----
#pragma unroll
        for (int kk = 0; kk < 16; ++kk) {
            float a0 = As[kk][ry * 4 + 0];
            float a1 = As[kk][ry * 4 + 1];
            float a2 = As[kk][ry * 4 + 2];
            float a3 = As[kk][ry * 4 + 3];
            float4 b0 = *reinterpret_cast<const float4*>(&Bs[kk][cx * 8]);
            float4 b1 = *reinterpret_cast<const float4*>(&Bs[kk][cx * 8 + 4]);
            float bb[8] = {b0.x, b0.y, b0.z, b0.w, b1.x, b1.y, b1.z, b1.w};
#pragma unroll
            for (int j = 0; j < 8; j++) {
                acc[0][j] = fmaf(a0, bb[j], acc[0][j]);
                acc[1][j] = fmaf(a1, bb[j], acc[1][j]);
                acc[2][j] = fmaf(a2, bb[j], acc[2][j]);
                acc[3][j] = fmaf(a3, bb[j], acc[3][j]);
            }
        }
        __syncthreads();
    }

    // ---- epilogue ----
    if (ACT == 3) {
        float pac[4] = {0.f, 0.f, 0.f, 0.f};
#pragma unroll
        for (int i = 0; i < 4; i++) {
#pragma unroll
            for (int j = 0; j < 8; j++) {
                int c = cx * 8 + j;
                float f = tanhf(acc[i][j] + bias[c]);
                pac[i] = fmaf(f, Wp[c], pac[i]);
            }
            pbuf[ry * 4 + i][cx] = pac[i];
        }
        __syncthreads();
        if (t < 64) {
            float s = bp[0];
#pragma unroll
            for (int x = 0; x < 16; x++) s += pbuf[t][x];
            C[bi * 64 + t] = 1.f / (1.f + __expf(-s));
        }
    } else {
#pragma unroll
        for (int i = 0; i < 4; i++) {
            int row = bi * 64 + ry * 4 + i;
#pragma unroll
            for (int j = 0; j < 8; j++) {
                int c = cx * 8 + j;
                float v = acc[i][j] + bias[c];
                if (ACT == 1) v = 1.f / (1.f + __expf(-v));
                if (ACT == 2) v = tanhf(v);
                C[(size_t)row * 128 + c] = v;
            }
        }
    }
}

// ---------------------------------------------------------------------------
// w = softmax(k @ Mk^T) : per-CTA 32 rows, 128 threads, STATIC smem (43.3 KB).
//   sm_k : 32 x 132 floats (k tile, padded)   [reused as logits, pitch 52]
//   sm_m : 50 x 132 floats (Mk, padded)
// ---------------------------------------------------------------------------
__global__ __launch_bounds__(128) void wsoftmax_kernel(
    const float* __restrict__ K, const float* __restrict__ Mk,
    float* __restrict__ Wout)
{
    __shared__ float sm_k[32 * 132];
    __shared__ float sm_m[50 * 132];
    float4* kt4 = reinterpret_cast<float4*>(sm_k);   // pitch 33 float4
    float4* mk4 = reinterpret_cast<float4*>(sm_m);
    float*  lg  = sm_k;                              // reuse (pitch 52)

    const int t  = threadIdx.x;
    const int bi = blockIdx.x;   // 400 blocks of 32 rows

    for (int e = t; e < 32 * 32; e += 128) {
        int rw = e >> 5, c4 = e & 31;
        kt4[rw * 33 + c4] =
            *reinterpret_cast<const float4*>(K + ((size_t)(bi * 32 + rw)) * 128 + c4 * 4);
    }
    for (int e = t; e < 50 * 32; e += 128) {
        int m = e >> 5, c4 = e & 31;
        mk4[m * 33 + c4] = *reinterpret_cast<const float4*>(Mk + (size_t)m * 128 + c4 * 4);
    }
    __syncthreads();

    const int row = t >> 2;
    const int mg  = t & 3;
    const int m0  = (mg < 2) ? mg * 13 : 26 + (mg - 2) * 12;
    const int cnt = (mg < 2) ? 13 : 12;

    float s[13];
#pragma unroll
    for (int j = 0; j < 13; j++) s[j] = 0.f;

    for (int c4 = 0; c4 < 32; ++c4) {
        float4 kv = kt4[row * 33 + c4];
#pragma unroll
        for (int j = 0; j < 13; j++) {
            if (j < cnt) {
                float4 mv = mk4[(m0 + j) * 33 + c4];
                s[j] = fmaf(kv.x, mv.x,
                        fmaf(kv.y, mv.y,
                         fmaf(kv.z, mv.z,
                          fmaf(kv.w, mv.w, s[j]))));
            }
        }
    }
    __syncthreads();   // done reading kt, safe to overwrite with logits
#pragma unroll
    for (int j = 0; j < 13; j++)
        if (j < cnt) lg[row * 52 + m0 + j] = s[j];
    __syncthreads();

    if (t < 32) {
        float mx = -1e30f;
        for (int m = 0; m < 50; m++) mx = fmaxf(mx, lg[t * 52 + m]);
        float sum = 0.f;
        for (int m = 0; m < 50; m++) sum += __expf(lg[t * 52 + m] - mx);
        float inv = 1.f / sum;
        size_t ob = (size_t)(bi * 32 + t) * 64;
        for (int m = 0; m < 50; m++)
            Wout[ob + m] = __expf(lg[t * 52 + m] - mx) * inv;
    }
}

// ---------------------------------------------------------------------------
// Sequential memory scan. Grid (4 d-chunks, 64 batches), 128 threads.
// Thread (dl, mg): owns Mv[m0..m0+cnt)[d] in registers.
//   r_t[d]  = sum_m w[m] * Mv[m][d]            (read BEFORE update)
//   Mv[m][d] += w[m] * (a[d] - e[d]*Mv[m][d])
// ---------------------------------------------------------------------------
__global__ __launch_bounds__(128) void scan_kernel(
    const float* __restrict__ Wm, const float* __restrict__ E,
    const float* __restrict__ Aa, const float* __restrict__ Mv0,
    float* __restrict__ R)
{
    const int b  = blockIdx.y;
    const int dc = blockIdx.x;
    const int t  = threadIdx.x;
    const int dl = t & 31;
    const int mg = t >> 5;
    const int d  = dc * 32 + dl;
    const int m0  = (mg < 2) ? mg * 13 : 26 + (mg - 2) * 12;
    const int cnt = (mg < 2) ? 13 : 12;

    float mv[13];
#pragma unroll
    for (int i = 0; i < 13; i++)
        if (i < cnt) mv[i] = Mv0[(size_t)(m0 + i) * 128 + d];

    __shared__ float ws[2][52];
    __shared__ float ps[2][4][32];

    const size_t rowbase = (size_t)b * 200;
    for (int tt = 0; tt < 200; ++tt) {
        const int pb = tt & 1;
        const size_t row = rowbase + tt;
        if (t < 50) ws[pb][t] = Wm[row * 64 + t];
        float ed = E[row * 128 + d];
        float ad = Aa[row * 128 + d];
        __syncthreads();

        float partial = 0.f;
#pragma unroll
        for (int i = 0; i < 13; i++)
            if (i < cnt) partial = fmaf(ws[pb][m0 + i], mv[i], partial);
        ps[pb][mg][dl] = partial;
        __syncthreads();

        if (mg == 0)
            R[row * 128 + d] = ps[pb][0][dl] + ps[pb][1][dl] + ps[pb][2][dl] + ps[pb][3][dl];

#pragma unroll
        for (int i = 0; i < 13; i++) {
            if (i < cnt) {
                float wm = ws[pb][m0 + i];
                mv[i] = fmaf(wm, fmaf(-mv[i], ed, ad), mv[i]);
            }
        }
    }
}

// ---------------------------------------------------------------------------
extern "C" void kernel_launch(void* const* d_in, const int* in_sizes, int n_in,
                              void* d_out, int out_size)
{
    const int*   q     = (const int*)d_in[0];
    const int*   r     = (const int*)d_in[1];
    // d_in[2] = diff (unused by reference)
    const float* k_emb = (const float*)d_in[3];
    const float* v_emb = (const float*)d_in[4];
    const float* W1 = (const float*)d_in[5];
    const float* b1 = (const float*)d_in[6];
    const float* W2 = (const float*)d_in[7];
    const float* b2 = (const float*)d_in[8];
    const float* Mk  = (const float*)d_in[9];
    const float* Mv0 = (const float*)d_in[10];
    const float* We = (const float*)d_in[11];
    const float* be = (const float*)d_in[12];
    const float* Wa = (const float*)d_in[13];
    const float* ba = (const float*)d_in[14];
    const float* Wf = (const float*)d_in[15];
    const float* bf = (const float*)d_in[16];
    const float* Wp = (const float*)d_in[17];
    const float* bp = (const float*)d_in[18];
    float* out = (float*)d_out;

    float *pk, *pv, *pe, *pa, *pr, *pw;
    cudaGetSymbolAddress((void**)&pk, g_k);
    cudaGetSymbolAddress((void**)&pv, g_v);
    cudaGetSymbolAddress((void**)&pe, g_e);
    cudaGetSymbolAddress((void**)&pa, g_a);
    cudaGetSymbolAddress((void**)&pr, g_reads);
    cudaGetSymbolAddress((void**)&pw, g_w);

    // k and v projections (gathered, K=512)
    gemm64x128<512, 1, 0><<<200, 256>>>(k_emb, nullptr, q, r, W1, b1, pk, nullptr, nullptr);
    gemm64x128<512, 2, 0><<<200, 256>>>(v_emb, nullptr, q, r, W2, b2, pv, nullptr, nullptr);

    // attention weights
    wsoftmax_kernel<<<400, 128>>>(pk, Mk, pw);

    // erase / add
    gemm64x128<128, 0, 1><<<200, 256>>>(pv, nullptr, q, r, We, be, pe, nullptr, nullptr);
    gemm64x128<128, 0, 2><<<200, 256>>>(pv, nullptr, q, r, Wa, ba, pa, nullptr, nullptr);

    // sequential memory scan
    scan_kernel<<<dim3(4, 64), 128>>>(pw, pe, pa, Mv0, pr);

    // fused head: p = sigmoid(tanh([reads|k] @ Wf + bf) @ Wp + bp)
    gemm64x128<256, 0, 3><<<200, 256>>>(pr, pk, q, r, Wf, bf, out, Wp, bp);
}

// round 4
// speedup vs baseline: 1.2424x; 1.2424x over previous
#include <cuda_runtime.h>
#include <cuda_bf16.h>
#include <math.h>

// ---------------------------------------------------------------------------
// DKVMN fused: B=64, L=200, D=128, M=50, FIX=512. Rows = 12800.
//  kernel kpath : k = k_emb[q]@W1+b1 ; w = softmax(k@Mk^T)   (fused)
//  kernel vpath : v = v_emb[q+1e4 r]@W2+b2 ; e = sig(v@We+be); a = tanh(v@Wa+ba)
//  kernel scan  : r_t = w_t . Mv ; Mv += w (x) (a - e*Mv)
//  kernel head  : p = sigmoid(tanh([reads|k]@Wf+bf) @ Wp + bp)
// Tiles: 32 rows x 128 cols, 128 threads, BK=16, double-buffered smem.
// ---------------------------------------------------------------------------

#define NROWS 12800

__device__ float g_k[NROWS * 128];
__device__ float g_e[NROWS * 128];
__device__ float g_a[NROWS * 128];
__device__ float g_reads[NROWS * 128];
__device__ float g_w[NROWS * 64];   // pitch 64, 50 valid

// ---------------------------------------------------------------------------
// Double-buffered mainloop. A from global (aA row-base ptr for this thread's
// load row; cols kt*16+c4*4). For kt >= SPLIT, read aB instead (concat case).
// acc[4][8]: rows ry*4+i, cols cx*8+j.
// ---------------------------------------------------------------------------
template <int NT, int SPLIT>
__device__ __forceinline__ void mm_loop(
    const float* __restrict__ aA, const float* __restrict__ aB,
    const float* __restrict__ W, float (&acc)[4][8],
    float (*As)[32][17], float (*Bs)[16][128], int t, int cx, int ry)
{
    const int lr4 = (t & 3) * 4;     // c4*4 : column within 16-wide k-slab
    const int lrow = t >> 2;

    float4 ar;
    float4 br[4];

    auto ldA = [&](int kt) -> float4 {
        const float* p = (kt < SPLIT) ? (aA + kt * 16) : (aB + (kt - SPLIT) * 16);
        return *reinterpret_cast<const float4*>(p + lr4);
    };
    auto ldB = [&](int kt, int u) -> float4 {
        int e = t + u * 128;
        int rr = e >> 5, cb = e & 31;
        return *reinterpret_cast<const float4*>(W + (size_t)(kt * 16 + rr) * 128 + cb * 4);
    };
    auto stAB = [&](int buf) {
        As[buf][lrow][lr4 + 0] = ar.x;
        As[buf][lrow][lr4 + 1] = ar.y;
        As[buf][lrow][lr4 + 2] = ar.z;
        As[buf][lrow][lr4 + 3] = ar.w;
#pragma unroll
        for (int u = 0; u < 4; ++u) {
            int e = t + u * 128;
            int rr = e >> 5, cb = e & 31;
            *reinterpret_cast<float4*>(&Bs[buf][rr][cb * 4]) = br[u];
        }
    };

    ar = ldA(0);
#pragma unroll
    for (int u = 0; u < 4; ++u) br[u] = ldB(0, u);
    stAB(0);
    __syncthreads();

#pragma unroll 1
    for (int kt = 0; kt < NT; ++kt) {
        const int cur = kt & 1, nxt = cur ^ 1;
        if (kt + 1 < NT) {
            ar = ldA(kt + 1);
#pragma unroll
            for (int u = 0; u < 4; ++u) br[u] = ldB(kt + 1, u);
        }
#pragma unroll
        for (int kk = 0; kk < 16; ++kk) {
            float a0 = As[cur][ry * 4 + 0][kk];
            float a1 = As[cur][ry * 4 + 1][kk];
            float a2 = As[cur][ry * 4 + 2][kk];
            float a3 = As[cur][ry * 4 + 3][kk];
            float4 b0 = *reinterpret_cast<const float4*>(&Bs[cur][kk][cx * 8]);
            float4 b1 = *reinterpret_cast<const float4*>(&Bs[cur][kk][cx * 8 + 4]);
            float bb[8] = {b0.x, b0.y, b0.z, b0.w, b1.x, b1.y, b1.z, b1.w};
#pragma unroll
            for (int j = 0; j < 8; ++j) {
                acc[0][j] = fmaf(a0, bb[j], acc[0][j]);
                acc[1][j] = fmaf(a1, bb[j], acc[1][j]);
                acc[2][j] = fmaf(a2, bb[j], acc[2][j]);
                acc[3][j] = fmaf(a3, bb[j], acc[3][j]);
            }
        }
        if (kt + 1 < NT) stAB(nxt);
        __syncthreads();
    }
}

// Same loop but A resident in smem (Vs[32][132]); only B is double-buffered.
template <int NT>
__device__ __forceinline__ void mm_loop_smemA(
    const float (*Vs)[132], const float* __restrict__ W, float (&acc)[4][8],
    float (*Bs)[16][128], int t, int cx, int ry)
{
    float4 br[4];
    auto ldB = [&](int kt, int u) -> float4 {
        int e = t + u * 128;
        int rr = e >> 5, cb = e & 31;
        return *reinterpret_cast<const float4*>(W + (size_t)(kt * 16 + rr) * 128 + cb * 4);
    };
    auto stB = [&](int buf) {
#pragma unroll
        for (int u = 0; u < 4; ++u) {
            int e = t + u * 128;
            int rr = e >> 5, cb = e & 31;
            *reinterpret_cast<float4*>(&Bs[buf][rr][cb * 4]) = br[u];
        }
    };
#pragma unroll
    for (int u = 0; u < 4; ++u) br[u] = ldB(0, u);
    stB(0);
    __syncthreads();

#pragma unroll 1
    for (int kt = 0; kt < NT; ++kt) {
        const int cur = kt & 1, nxt = cur ^ 1;
        if (kt + 1 < NT) {
#pragma unroll
            for (int u = 0; u < 4; ++u) br[u] = ldB(kt + 1, u);
        }
#pragma unroll
        for (int kk = 0; kk < 16; ++kk) {
            float a0 = Vs[ry * 4 + 0][kt * 16 + kk];
            float a1 = Vs[ry * 4 + 1][kt * 16 + kk];
            float a2 = Vs[ry * 4 + 2][kt * 16 + kk];
            float a3 = Vs[ry * 4 + 3][kt * 16 + kk];
            float4 b0 = *reinterpret_cast<const float4*>(&Bs[cur][kk][cx * 8]);
            float4 b1 = *reinterpret_cast<const float4*>(&Bs[cur][kk][cx * 8 + 4]);
            float bb[8] = {b0.x, b0.y, b0.z, b0.w, b1.x, b1.y, b1.z, b1.w};
#pragma unroll
            for (int j = 0; j < 8; ++j) {
                acc[0][j] = fmaf(a0, bb[j], acc[0][j]);
                acc[1][j] = fmaf(a1, bb[j], acc[1][j]);
                acc[2][j] = fmaf(a2, bb[j], acc[2][j]);
                acc[3][j] = fmaf(a3, bb[j], acc[3][j]);
            }
        }
        if (kt + 1 < NT) stB(nxt);
        __syncthreads();
    }
}

// ---------------------------------------------------------------------------
// kpath: k = k_emb[q]@W1+b1 (K=512), then fused w = softmax(k @ Mk^T).
// ---------------------------------------------------------------------------
struct MMBufs { float As[2][32][17]; float Bs[2][16][128]; };
struct SMBufs { float kt[32][132]; float mk[50][132]; };
union KUnion { MMBufs mm; SMBufs sm; };

__global__ __launch_bounds__(128) void kpath_kernel(
    const float* __restrict__ k_emb, const int* __restrict__ q,
    const float* __restrict__ W1, const float* __restrict__ b1,
    const float* __restrict__ Mk, float* __restrict__ gk,
    float* __restrict__ gw)
{
    __shared__ KUnion s;
    const int t = threadIdx.x, bi = blockIdx.x;
    const int cx = t & 15, ry = t >> 4;
    const int lrow = t >> 2;
    const int grow = bi * 32 + lrow;
    const float* aA = k_emb + (size_t)q[grow] * 512;

    float acc[4][8];
#pragma unroll
    for (int i = 0; i < 4; i++)
#pragma unroll
        for (int j = 0; j < 8; j++) acc[i][j] = 0.f;

    mm_loop<32, 32>(aA, nullptr, W1, acc, s.mm.As, s.mm.Bs, t, cx, ry);

    // write k to global + smem tile (union repurposed after last barrier)
#pragma unroll
    for (int i = 0; i < 4; i++) {
        int row = ry * 4 + i;
        float4 o0, o1;
        o0.x = acc[i][0] + b1[cx * 8 + 0]; o0.y = acc[i][1] + b1[cx * 8 + 1];
        o0.z = acc[i][2] + b1[cx * 8 + 2]; o0.w = acc[i][3] + b1[cx * 8 + 3];
        o1.x = acc[i][4] + b1[cx * 8 + 4]; o1.y = acc[i][5] + b1[cx * 8 + 5];
        o1.z = acc[i][6] + b1[cx * 8 + 6]; o1.w = acc[i][7] + b1[cx * 8 + 7];
        *reinterpret_cast<float4*>(&s.sm.kt[row][cx * 8]) = o0;
        *reinterpret_cast<float4*>(&s.sm.kt[row][cx * 8 + 4]) = o1;
        *reinterpret_cast<float4*>(gk + (size_t)(bi * 32 + row) * 128 + cx * 8) = o0;
        *reinterpret_cast<float4*>(gk + (size_t)(bi * 32 + row) * 128 + cx * 8 + 4) = o1;
    }
    // load Mk (50 x 128) into smem, pitch 132
    {
        float4* mk4 = reinterpret_cast<float4*>(&s.sm.mk[0][0]);
        for (int e = t; e < 50 * 32; e += 128) {
            int m = e >> 5, c4 = e & 31;
            mk4[m * 33 + c4] = *reinterpret_cast<const float4*>(Mk + (size_t)m * 128 + c4 * 4);
        }
    }
    __syncthreads();

    // logits: 32 rows x 50 ; thread = (row, mgroup)
    const int row = t >> 2;
    const int mg = t & 3;
    const int m0 = (mg < 2) ? mg * 13 : 26 + (mg - 2) * 12;
    const int cnt = (mg < 2) ? 13 : 12;
    const float4* kt4 = reinterpret_cast<const float4*>(&s.sm.kt[0][0]);
    const float4* mk4 = reinterpret_cast<const float4*>(&s.sm.mk[0][0]);

    float sdot[13];
#pragma unroll
    for (int j = 0; j < 13; j++) sdot[j] = 0.f;
    for (int c4 = 0; c4 < 32; ++c4) {
        float4 kv = kt4[row * 33 + c4];
#pragma unroll
        for (int j = 0; j < 13; j++) {
            if (j < cnt) {
                float4 mv = mk4[(m0 + j) * 33 + c4];
                sdot[j] = fmaf(kv.x, mv.x, fmaf(kv.y, mv.y,
                           fmaf(kv.z, mv.z, fmaf(kv.w, mv.w, sdot[j]))));
            }
        }
    }
    __syncthreads();   // done reading kt; reuse as logits (pitch 52)
    float* lg = &s.sm.kt[0][0];
#pragma unroll
    for (int j = 0; j < 13; j++)
        if (j < cnt) lg[row * 52 + m0 + j] = sdot[j];
    __syncthreads();

    if (t < 32) {
        float mx = -1e30f;
        for (int m = 0; m < 50; m++) mx = fmaxf(mx, lg[t * 52 + m]);
        float sum = 0.f;
        for (int m = 0; m < 50; m++) sum += __expf(lg[t * 52 + m] - mx);
        float inv = 1.f / sum;
        size_t ob = (size_t)(bi * 32 + t) * 64;
        for (int m = 0; m < 50; m++)
            gw[ob + m] = __expf(lg[t * 52 + m] - mx) * inv;
    }
}

// ---------------------------------------------------------------------------
// vpath: v = v_emb[q + 10000 r]@W2+b2 (K=512, never leaves chip),
//        e = sigmoid(v@We+be), a = tanh(v@Wa+ba).
// ---------------------------------------------------------------------------
__global__ __launch_bounds__(128) void vpath_kernel(
    const float* __restrict__ v_emb, const int* __restrict__ q,
    const int* __restrict__ r, const float* __restrict__ W2,
    const float* __restrict__ b2, const float* __restrict__ We,
    const float* __restrict__ be, const float* __restrict__ Wa,
    const float* __restrict__ ba, float* __restrict__ ge,
    float* __restrict__ ga)
{
    __shared__ float As[2][32][17];
    __shared__ float Bs[2][16][128];
    __shared__ float Vs[32][132];

    const int t = threadIdx.x, bi = blockIdx.x;
    const int cx = t & 15, ry = t >> 4;
    const int lrow = t >> 2;
    const int grow = bi * 32 + lrow;
    const size_t arow = (size_t)q[grow] + (size_t)10000 * (size_t)r[grow];
    const float* aA = v_emb + arow * 512;

    float acc[4][8];
#pragma unroll
    for (int i = 0; i < 4; i++)
#pragma unroll
        for (int j = 0; j < 8; j++) acc[i][j] = 0.f;

    mm_loop<32, 32>(aA, nullptr, W2, acc, As, Bs, t, cx, ry);

#pragma unroll
    for (int i = 0; i < 4; i++)
#pragma unroll
        for (int j = 0; j < 8; j++)
            Vs[ry * 4 + i][cx * 8 + j] = acc[i][j] + b2[cx * 8 + j];
    __syncthreads();

    // e = sigmoid(v @ We + be)
#pragma unroll
    for (int i = 0; i < 4; i++)
#pragma unroll
        for (int j = 0; j < 8; j++) acc[i][j] = 0.f;
    mm_loop_smemA<8>(Vs, We, acc, Bs, t, cx, ry);
#pragma unroll
    for (int i = 0; i < 4; i++) {
        size_t row = (size_t)(bi * 32 + ry * 4 + i);
        float4 o0, o1;
        o0.x = 1.f / (1.f + __expf(-(acc[i][0] + be[cx * 8 + 0])));
        o0.y = 1.f / (1.f + __expf(-(acc[i][1] + be[cx * 8 + 1])));
        o0.z = 1.f / (1.f + __expf(-(acc[i][2] + be[cx * 8 + 2])));
        o0.w = 1.f / (1.f + __expf(-(acc[i][3] + be[cx * 8 + 3])));
        o1.x = 1.f / (1.f + __expf(-(acc[i][4] + be[cx * 8 + 4])));
        o1.y = 1.f / (1.f + __expf(-(acc[i][5] + be[cx * 8 + 5])));
        o1.z = 1.f / (1.f + __expf(-(acc[i][6] + be[cx * 8 + 6])));
        o1.w = 1.f / (1.f + __expf(-(acc[i][7] + be[cx * 8 + 7])));
        *reinterpret_cast<float4*>(ge + row * 128 + cx * 8) = o0;
        *reinterpret_cast<float4*>(ge + row * 128 + cx * 8 + 4) = o1;
    }

    // a = tanh(v @ Wa + ba)
#pragma unroll
    for (int i = 0; i < 4; i++)
#pragma unroll
        for (int j = 0; j < 8; j++) acc[i][j] = 0.f;
    mm_loop_smemA<8>(Vs, Wa, acc, Bs, t, cx, ry);
#pragma unroll
    for (int i = 0; i < 4; i++) {
        size_t row = (size_t)(bi * 32 + ry * 4 + i);
        float4 o0, o1;
        o0.x = tanhf(acc[i][0] + ba[cx * 8 + 0]);
        o0.y = tanhf(acc[i][1] + ba[cx * 8 + 1]);
        o0.z = tanhf(acc[i][2] + ba[cx * 8 + 2]);
        o0.w = tanhf(acc[i][3] + ba[cx * 8 + 3]);
        o1.x = tanhf(acc[i][4] + ba[cx * 8 + 4]);
        o1.y = tanhf(acc[i][5] + ba[cx * 8 + 5]);
        o1.z = tanhf(acc[i][6] + ba[cx * 8 + 6]);
        o1.w = tanhf(acc[i][7] + ba[cx * 8 + 7]);
        *reinterpret_cast<float4*>(ga + row * 128 + cx * 8) = o0;
        *reinterpret_cast<float4*>(ga + row * 128 + cx * 8 + 4) = o1;
    }
}

// ---------------------------------------------------------------------------
// head: p = sigmoid( tanh([reads|k] @ Wf + bf) @ Wp + bp )  (K=256 concat)
// ---------------------------------------------------------------------------
__global__ __launch_bounds__(128) void head_kernel(
    const float* __restrict__ reads, const float* __restrict__ k,
    const float* __restrict__ Wf, const float* __restrict__ bf,
    const float* __restrict__ Wp, const float* __restrict__ bp,
    float* __restrict__ out)
{
    __shared__ float As[2][32][17];
    __shared__ float Bs[2][16][128];
    __shared__ float pbuf[32][17];

    const int t = threadIdx.x, bi = blockIdx.x;
    const int cx = t & 15, ry = t >> 4;
    const int lrow = t >> 2;
    const size_t grow = (size_t)(bi * 32 + lrow);
    const float* aA = reads + grow * 128;
    const float* aB = k + grow * 128;

    float acc[4][8];
#pragma unroll
    for (int i = 0; i < 4; i++)
#pragma unroll
        for (int j = 0; j < 8; j++) acc[i][j] = 0.f;

    mm_loop<16, 8>(aA, aB, Wf, acc, As, Bs, t, cx, ry);

#pragma unroll
    for (int i = 0; i < 4; i++) {
        float pac = 0.f;
#pragma unroll
        for (int j = 0; j < 8; j++) {
            int c = cx * 8 + j;
            float f = tanhf(acc[i][j] + bf[c]);
            pac = fmaf(f, Wp[c], pac);
        }
        pbuf[ry * 4 + i][cx] = pac;
    }
    __syncthreads();
    if (t < 32) {
        float s = bp[0];
#pragma unroll
        for (int x = 0; x < 16; x++) s += pbuf[t][x];
        out[bi * 32 + t] = 1.f / (1.f + __expf(-s));
    }
}

// ---------------------------------------------------------------------------
// Sequential memory scan (unchanged from passing version).
// ---------------------------------------------------------------------------
__global__ __launch_bounds__(128) void scan_kernel(
    const float* __restrict__ Wm, const float* __restrict__ E,
    const float* __restrict__ Aa, const float* __restrict__ Mv0,
    float* __restrict__ R)
{
    const int b  = blockIdx.y;
    const int dc = blockIdx.x;
    const int t  = threadIdx.x;
    const int dl = t & 31;
    const int mg = t >> 5;
    const int d  = dc * 32 + dl;
    const int m0  = (mg < 2) ? mg * 13 : 26 + (mg - 2) * 12;
    const int cnt = (mg < 2) ? 13 : 12;

    float mv[13];
#pragma unroll
    for (int i = 0; i < 13; i++)
        if (i < cnt) mv[i] = Mv0[(size_t)(m0 + i) * 128 + d];

    __shared__ float ws[2][52];
    __shared__ float ps[2][4][32];

    const size_t rowbase = (size_t)b * 200;
    for (int tt = 0; tt < 200; ++tt) {
        const int pb = tt & 1;
        const size_t row = rowbase + tt;
        if (t < 50) ws[pb][t] = Wm[row * 64 + t];
        float ed = E[row * 128 + d];
        float ad = Aa[row * 128 + d];
        __syncthreads();

        float partial = 0.f;
#pragma unroll
        for (int i = 0; i < 13; i++)
            if (i < cnt) partial = fmaf(ws[pb][m0 + i], mv[i], partial);
        ps[pb][mg][dl] = partial;
        __syncthreads();

        if (mg == 0)
            R[row * 128 + d] = ps[pb][0][dl] + ps[pb][1][dl] + ps[pb][2][dl] + ps[pb][3][dl];

#pragma unroll
        for (int i = 0; i < 13; i++) {
            if (i < cnt) {
                float wm = ws[pb][m0 + i];
                mv[i] = fmaf(wm, fmaf(-mv[i], ed, ad), mv[i]);
            }
        }
    }
}

// ---------------------------------------------------------------------------
extern "C" void kernel_launch(void* const* d_in, const int* in_sizes, int n_in,
                              void* d_out, int out_size)
{
    const int*   q     = (const int*)d_in[0];
    const int*   r     = (const int*)d_in[1];
    // d_in[2] = diff (unused)
    const float* k_emb = (const float*)d_in[3];
    const float* v_emb = (const float*)d_in[4];
    const float* W1 = (const float*)d_in[5];
    const float* b1 = (const float*)d_in[6];
    const float* W2 = (const float*)d_in[7];
    const float* b2 = (const float*)d_in[8];
    const float* Mk  = (const float*)d_in[9];
    const float* Mv0 = (const float*)d_in[10];
    const float* We = (const float*)d_in[11];
    const float* be = (const float*)d_in[12];
    const float* Wa = (const float*)d_in[13];
    const float* ba = (const float*)d_in[14];
    const float* Wf = (const float*)d_in[15];
    const float* bf = (const float*)d_in[16];
    const float* Wp = (const float*)d_in[17];
    const float* bp = (const float*)d_in[18];
    float* out = (float*)d_out;

    float *pk, *pe, *pa, *pr, *pw;
    cudaGetSymbolAddress((void**)&pk, g_k);
    cudaGetSymbolAddress((void**)&pe, g_e);
    cudaGetSymbolAddress((void**)&pa, g_a);
    cudaGetSymbolAddress((void**)&pr, g_reads);
    cudaGetSymbolAddress((void**)&pw, g_w);

    kpath_kernel<<<400, 128>>>(k_emb, q, W1, b1, Mk, pk, pw);
    vpath_kernel<<<400, 128>>>(v_emb, q, r, W2, b2, We, be, Wa, ba, pe, pa);
    scan_kernel<<<dim3(4, 64), 128>>>(pw, pe, pa, Mv0, pr);
    head_kernel<<<400, 128>>>(pr, pk, Wf, bf, Wp, bp, out);
}

// round 5
// speedup vs baseline: 1.5939x; 1.2829x over previous
#include <cuda_runtime.h>
#include <cuda_bf16.h>
#include <math.h>

// ---------------------------------------------------------------------------
// DKVMN: B=64, L=200, D=128, M=50, FIX=512. Rows = 12800.
//   k = k_emb[q]@W1+b1            gemm64x64<512,1,0>
//   v = v_emb[q+1e4 r]@W2+b2      gemm64x64<512,2,0>
//   w = softmax(k@Mk^T)           wsoftmax
//   e = sigmoid(v@We+be)          gemm64x64<128,0,1>
//   a = tanh(v@Wa+ba)             gemm64x64<128,0,2>
//   scan: r_t = w_t.Mv ; Mv += w (x) (a - e*Mv)
//   p = sigmoid(tanh([reads|k]@Wf+bf)@Wp+bp)   head (64x128 tile)
// ---------------------------------------------------------------------------

#define NROWS 12800

__device__ float g_k[NROWS * 128];
__device__ float g_v[NROWS * 128];
__device__ float g_e[NROWS * 128];
__device__ float g_a[NROWS * 128];
__device__ float g_reads[NROWS * 128];
__device__ float g_w[NROWS * 64];   // pitch 64, 50 valid

__device__ __forceinline__ float fast_tanh(float x) {
    float y;
    asm("tanh.approx.f32 %0, %1;" : "=f"(y) : "f"(x));
    return y;
}
__device__ __forceinline__ float fast_sig(float x) {
    return 0.5f * fast_tanh(0.5f * x) + 0.5f;
}

// ---------------------------------------------------------------------------
// 64x64 tile GEMM, 64 threads, 8x8 per thread, double-buffered BK=16.
// grid = (2 col-halves, 200 row-tiles).
// IDX: 0 direct (lda=128), 1 gather q (lda=512), 2 gather q+10000r (lda=512)
// ACT: 0 none, 1 sigmoid, 2 tanh
// ---------------------------------------------------------------------------
template <int KDIM, int IDX, int ACT>
__global__ __launch_bounds__(64) void gemm64x64_kernel(
    const float* __restrict__ A, const int* __restrict__ qi,
    const int* __restrict__ ri, const float* __restrict__ W,
    const float* __restrict__ bias, float* __restrict__ C)
{
    __shared__ float As[2][16][68];   // [kk][row] transposed
    __shared__ float Bs[2][16][68];   // [kk][col]

    const int t  = threadIdx.x;
    const int nb = blockIdx.x;        // column half (0/1)
    const int mb = blockIdx.y;        // 64-row tile
    const int cx = t & 7;             // 8 col groups of 8
    const int ry = t >> 3;            // 8 row groups of 8
    const int c4 = t & 3;             // A-load col slot
    const int r0 = t >> 2;            // A-load base row (0..15)

    const float* aptr[4];
#pragma unroll
    for (int u = 0; u < 4; ++u) {
        int rr = mb * 64 + r0 + u * 16;
        size_t arow;
        if (IDX == 1)      arow = (size_t)qi[rr];
        else if (IDX == 2) arow = (size_t)qi[rr] + (size_t)10000 * (size_t)ri[rr];
        else               arow = (size_t)rr;
        aptr[u] = A + arow * (size_t)((IDX == 0) ? 128 : 512);
    }
    const float* Wb = W + nb * 64;

    float4 ar[4], br[4];
    auto ldA = [&](int kt) {
#pragma unroll
        for (int u = 0; u < 4; ++u)
            ar[u] = *reinterpret_cast<const float4*>(aptr[u] + kt * 16 + c4 * 4);
    };
    auto ldB = [&](int kt) {
#pragma unroll
        for (int u = 0; u < 4; ++u) {
            int e = t + u * 64;
            int rr = e >> 4, cb = e & 15;
            br[u] = *reinterpret_cast<const float4*>(Wb + (size_t)(kt * 16 + rr) * 128 + cb * 4);
        }
    };
    auto stAB = [&](int buf) {
#pragma unroll
        for (int u = 0; u < 4; ++u) {
            int row = r0 + u * 16;
            As[buf][c4 * 4 + 0][row] = ar[u].x;
            As[buf][c4 * 4 + 1][row] = ar[u].y;
            As[buf][c4 * 4 + 2][row] = ar[u].z;
            As[buf][c4 * 4 + 3][row] = ar[u].w;
        }
#pragma unroll
        for (int u = 0; u < 4; ++u) {
            int e = t + u * 64;
            int rr = e >> 4, cb = e & 15;
            *reinterpret_cast<float4*>(&Bs[buf][rr][cb * 4]) = br[u];
        }
    };

    float acc[8][8];
#pragma unroll
    for (int i = 0; i < 8; i++)
#pragma unroll
        for (int j = 0; j < 8; j++) acc[i][j] = 0.f;

    constexpr int NT = KDIM / 16;
    ldA(0); ldB(0); stAB(0);
    __syncthreads();

#pragma unroll 1
    for (int kt = 0; kt < NT; ++kt) {
        const int cur = kt & 1, nxt = cur ^ 1;
        if (kt + 1 < NT) { ldA(kt + 1); ldB(kt + 1); }
#pragma unroll
        for (int kk = 0; kk < 16; ++kk) {
            float4 a0 = *reinterpret_cast<const float4*>(&As[cur][kk][ry * 8]);
            float4 a1 = *reinterpret_cast<const float4*>(&As[cur][kk][ry * 8 + 4]);
            float4 b0 = *reinterpret_cast<const float4*>(&Bs[cur][kk][cx * 8]);
            float4 b1 = *reinterpret_cast<const float4*>(&Bs[cur][kk][cx * 8 + 4]);
            float aa[8] = {a0.x, a0.y, a0.z, a0.w, a1.x, a1.y, a1.z, a1.w};
            float bb[8] = {b0.x, b0.y, b0.z, b0.w, b1.x, b1.y, b1.z, b1.w};
#pragma unroll
            for (int i = 0; i < 8; ++i)
#pragma unroll
                for (int j = 0; j < 8; ++j)
                    acc[i][j] = fmaf(aa[i], bb[j], acc[i][j]);
        }
        if (kt + 1 < NT) stAB(nxt);
        __syncthreads();
    }

    // epilogue
#pragma unroll
    for (int i = 0; i < 8; ++i) {
        size_t row = (size_t)(mb * 64 + ry * 8 + i);
        float o[8];
#pragma unroll
        for (int j = 0; j < 8; ++j) {
            int c = nb * 64 + cx * 8 + j;
            float vv = acc[i][j] + bias[c];
            if (ACT == 1) vv = fast_sig(vv);
            if (ACT == 2) vv = fast_tanh(vv);
            o[j] = vv;
        }
        float* dst = C + row * 128 + nb * 64 + cx * 8;
        *reinterpret_cast<float4*>(dst)     = make_float4(o[0], o[1], o[2], o[3]);
        *reinterpret_cast<float4*>(dst + 4) = make_float4(o[4], o[5], o[6], o[7]);
    }
}

// ---------------------------------------------------------------------------
// head: 64x128 tile, 128 threads, 8x8 per thread, K=256 ([reads|k] concat).
// Fused p = sigmoid(tanh(f) . Wp + bp).
// ---------------------------------------------------------------------------
__global__ __launch_bounds__(128) void head_kernel(
    const float* __restrict__ reads, const float* __restrict__ k,
    const float* __restrict__ Wf, const float* __restrict__ bf,
    const float* __restrict__ Wp, const float* __restrict__ bp,
    float* __restrict__ out)
{
    __shared__ float As[2][16][68];    // [kk][row 64]
    __shared__ float Bs[2][16][132];   // [kk][col 128]
    __shared__ float pbuf[64][17];

    const int t  = threadIdx.x;
    const int mb = blockIdx.x;
    const int cx = t & 15;
    const int ry = t >> 4;
    const int lrow = t >> 1;           // A-load row (0..63)
    const int c4b  = (t & 1) * 2;      // A-load slot base

    const float* aR = reads + (size_t)(mb * 64 + lrow) * 128;
    const float* aK = k     + (size_t)(mb * 64 + lrow) * 128;

    float4 ar[2], br[4];
    auto ldA = [&](int kt) {
#pragma unroll
        for (int u = 0; u < 2; ++u) {
            const float* base = (kt < 8) ? (aR + kt * 16) : (aK + (kt - 8) * 16);
            ar[u] = *reinterpret_cast<const float4*>(base + (c4b + u) * 4);
        }
    };
    auto ldB = [&](int kt) {
#pragma unroll
        for (int u = 0; u < 4; ++u) {
            int e = t + u * 128;
            int rr = e >> 5, cb = e & 31;
            br[u] = *reinterpret_cast<const float4*>(Wf + (size_t)(kt * 16 + rr) * 128 + cb * 4);
        }
    };
    auto stAB = [&](int buf) {
#pragma unroll
        for (int u = 0; u < 2; ++u) {
            int kkb = (c4b + u) * 4;
            As[buf][kkb + 0][lrow] = ar[u].x;
            As[buf][kkb + 1][lrow] = ar[u].y;
            As[buf][kkb + 2][lrow] = ar[u].z;
            As[buf][kkb + 3][lrow] = ar[u].w;
        }
#pragma unroll
        for (int u = 0; u < 4; ++u) {
            int e = t + u * 128;
            int rr = e >> 5, cb = e & 31;
            *reinterpret_cast<float4*>(&Bs[buf][rr][cb * 4]) = br[u];
        }
    };

    float acc[8][8];
#pragma unroll
    for (int i = 0; i < 8; i++)
#pragma unroll
        for (int j = 0; j < 8; j++) acc[i][j] = 0.f;

    ldA(0); ldB(0); stAB(0);
    __syncthreads();

#pragma unroll 1
    for (int kt = 0; kt < 16; ++kt) {
        const int cur = kt & 1, nxt = cur ^ 1;
        if (kt + 1 < 16) { ldA(kt + 1); ldB(kt + 1); }
#pragma unroll
        for (int kk = 0; kk < 16; ++kk) {
            float4 a0 = *reinterpret_cast<const float4*>(&As[cur][kk][ry * 8]);
            float4 a1 = *reinterpret_cast<const float4*>(&As[cur][kk][ry * 8 + 4]);
            float4 b0 = *reinterpret_cast<const float4*>(&Bs[cur][kk][cx * 8]);
            float4 b1 = *reinterpret_cast<const float4*>(&Bs[cur][kk][cx * 8 + 4]);
            float aa[8] = {a0.x, a0.y, a0.z, a0.w, a1.x, a1.y, a1.z, a1.w};
            float bb[8] = {b0.x, b0.y, b0.z, b0.w, b1.x, b1.y, b1.z, b1.w};
#pragma unroll
            for (int i = 0; i < 8; ++i)
#pragma unroll
                for (int j = 0; j < 8; ++j)
                    acc[i][j] = fmaf(aa[i], bb[j], acc[i][j]);
        }
        if (kt + 1 < 16) stAB(nxt);
        __syncthreads();
    }

    // fused epilogue: f = tanh(acc + bf); partial p-dot
#pragma unroll
    for (int i = 0; i < 8; ++i) {
        float pac = 0.f;
#pragma unroll
        for (int j = 0; j < 8; ++j) {
            int c = cx * 8 + j;
            float f = fast_tanh(acc[i][j] + bf[c]);
            pac = fmaf(f, Wp[c], pac);
        }
        pbuf[ry * 8 + i][cx] = pac;
    }
    __syncthreads();
    if (t < 64) {
        float s = bp[0];
#pragma unroll
        for (int x = 0; x < 16; ++x) s += pbuf[t][x];
        out[mb * 64 + t] = 1.f / (1.f + __expf(-s));
    }
}

// ---------------------------------------------------------------------------
// w = softmax(k @ Mk^T) : 32 rows/CTA, 128 threads (static smem).
// ---------------------------------------------------------------------------
__global__ __launch_bounds__(128) void wsoftmax_kernel(
    const float* __restrict__ K, const float* __restrict__ Mk,
    float* __restrict__ Wout)
{
    __shared__ float sm_k[32 * 132];
    __shared__ float sm_m[50 * 132];
    float4* kt4 = reinterpret_cast<float4*>(sm_k);   // pitch 33 float4
    float4* mk4 = reinterpret_cast<float4*>(sm_m);
    float*  lg  = sm_k;                              // reuse (pitch 52)

    const int t  = threadIdx.x;
    const int bi = blockIdx.x;

    for (int e = t; e < 32 * 32; e += 128) {
        int rw = e >> 5, c4 = e & 31;
        kt4[rw * 33 + c4] =
            *reinterpret_cast<const float4*>(K + ((size_t)(bi * 32 + rw)) * 128 + c4 * 4);
    }
    for (int e = t; e < 50 * 32; e += 128) {
        int m = e >> 5, c4 = e & 31;
        mk4[m * 33 + c4] = *reinterpret_cast<const float4*>(Mk + (size_t)m * 128 + c4 * 4);
    }
    __syncthreads();

    const int row = t >> 2;
    const int mg  = t & 3;
    const int m0  = (mg < 2) ? mg * 13 : 26 + (mg - 2) * 12;
    const int cnt = (mg < 2) ? 13 : 12;

    float s[13];
#pragma unroll
    for (int j = 0; j < 13; j++) s[j] = 0.f;

    for (int c4 = 0; c4 < 32; ++c4) {
        float4 kv = kt4[row * 33 + c4];
#pragma unroll
        for (int j = 0; j < 13; j++) {
            if (j < cnt) {
                float4 mv = mk4[(m0 + j) * 33 + c4];
                s[j] = fmaf(kv.x, mv.x, fmaf(kv.y, mv.y,
                        fmaf(kv.z, mv.z, fmaf(kv.w, mv.w, s[j]))));
            }
        }
    }
    __syncthreads();
#pragma unroll
    for (int j = 0; j < 13; j++)
        if (j < cnt) lg[row * 52 + m0 + j] = s[j];
    __syncthreads();

    if (t < 32) {
        float mx = -1e30f;
        for (int m = 0; m < 50; m++) mx = fmaxf(mx, lg[t * 52 + m]);
        float sum = 0.f;
        for (int m = 0; m < 50; m++) sum += __expf(lg[t * 52 + m] - mx);
        float inv = 1.f / sum;
        size_t ob = (size_t)(bi * 32 + t) * 64;
        for (int m = 0; m < 50; m++)
            Wout[ob + m] = __expf(lg[t * 52 + m] - mx) * inv;
    }
}

// ---------------------------------------------------------------------------
// Scan: grid (4 d-chunks, 64 batches), 128 threads.
// t = dl*4 + mg : mg in warp -> shfl reduction; 1 sync per step; prefetch.
// ---------------------------------------------------------------------------
__global__ __launch_bounds__(128) void scan_kernel(
    const float* __restrict__ Wm, const float* __restrict__ E,
    const float* __restrict__ Aa, const float* __restrict__ Mv0,
    float* __restrict__ R)
{
    const int b  = blockIdx.y;
    const int dc = blockIdx.x;
    const int t  = threadIdx.x;
    const int mg = t & 3;
    const int dl = t >> 2;
    const int d  = dc * 32 + dl;
    const int m0  = (mg < 2) ? mg * 13 : 26 + (mg - 2) * 12;
    const int cnt = (mg < 2) ? 13 : 12;

    float mv[13];
#pragma unroll
    for (int i = 0; i < 13; i++)
        if (i < cnt) mv[i] = Mv0[(size_t)(m0 + i) * 128 + d];

    __shared__ float ws[2][52];

    const size_t rowbase = (size_t)b * 200;
    const float* Ep = E  + rowbase * 128 + d;
    const float* Ap = Aa + rowbase * 128 + d;
    const float* Wp = Wm + rowbase * 64;
    float*       Rp = R  + rowbase * 128 + d;

    float ed, ad, wn = 0.f, en, an;
    if (t < 50) ws[0][t] = Wp[t];
    ed = Ep[0]; ad = Ap[0];
    __syncthreads();

    for (int tt = 0; tt < 200; ++tt) {
        const int pb = tt & 1;
        if (tt < 199) {
            if (t < 50) wn = Wp[(size_t)(tt + 1) * 64 + t];
            en = Ep[(size_t)(tt + 1) * 128];
            an = Ap[(size_t)(tt + 1) * 128];
        }

        float partial = 0.f;
#pragma unroll
        for (int i = 0; i < 13; i++)
            if (i < cnt) partial = fmaf(ws[pb][m0 + i], mv[i], partial);
        partial += __shfl_xor_sync(0xffffffffu, partial, 1);
        partial += __shfl_xor_sync(0xffffffffu, partial, 2);
        if (mg == 0) Rp[(size_t)tt * 128] = partial;

#pragma unroll
        for (int i = 0; i < 13; i++) {
            if (i < cnt) {
                float wm = ws[pb][m0 + i];
                mv[i] = fmaf(wm, fmaf(-mv[i], ed, ad), mv[i]);
            }
        }

        if (tt < 199) {
            if (t < 50) ws[pb ^ 1][t] = wn;
            ed = en; ad = an;
        }
        __syncthreads();
    }
}

// ---------------------------------------------------------------------------
extern "C" void kernel_launch(void* const* d_in, const int* in_sizes, int n_in,
                              void* d_out, int out_size)
{
    const int*   q     = (const int*)d_in[0];
    const int*   r     = (const int*)d_in[1];
    // d_in[2] = diff (unused)
    const float* k_emb = (const float*)d_in[3];
    const float* v_emb = (const float*)d_in[4];
    const float* W1 = (const float*)d_in[5];
    const float* b1 = (const float*)d_in[6];
    const float* W2 = (const float*)d_in[7];
    const float* b2 = (const float*)d_in[8];
    const float* Mk  = (const float*)d_in[9];
    const float* Mv0 = (const float*)d_in[10];
    const float* We = (const float*)d_in[11];
    const float* be = (const float*)d_in[12];
    const float* Wa = (const float*)d_in[13];
    const float* ba = (const float*)d_in[14];
    const float* Wf = (const float*)d_in[15];
    const float* bf = (const float*)d_in[16];
    const float* Wp = (const float*)d_in[17];
    const float* bp = (const float*)d_in[18];
    float* out = (float*)d_out;

    float *pk, *pv, *pe, *pa, *pr, *pw;
    cudaGetSymbolAddress((void**)&pk, g_k);
    cudaGetSymbolAddress((void**)&pv, g_v);
    cudaGetSymbolAddress((void**)&pe, g_e);
    cudaGetSymbolAddress((void**)&pa, g_a);
    cudaGetSymbolAddress((void**)&pr, g_reads);
    cudaGetSymbolAddress((void**)&pw, g_w);

    dim3 gg(2, 200);
    gemm64x64_kernel<512, 1, 0><<<gg, 64>>>(k_emb, q, r, W1, b1, pk);
    gemm64x64_kernel<512, 2, 0><<<gg, 64>>>(v_emb, q, r, W2, b2, pv);
    wsoftmax_kernel<<<400, 128>>>(pk, Mk, pw);
    gemm64x64_kernel<128, 0, 1><<<gg, 64>>>(pv, q, r, We, be, pe);
    gemm64x64_kernel<128, 0, 2><<<gg, 64>>>(pv, q, r, Wa, ba, pa);
    scan_kernel<<<dim3(4, 64), 128>>>(pw, pe, pa, Mv0, pr);
    head_kernel<<<200, 128>>>(pr, pk, Wf, bf, Wp, bp, out);
}